// round 14
// baseline (speedup 1.0000x reference)
#include <cuda_runtime.h>
#include <cuda_fp16.h>
#include <math.h>
#include <stdint.h>

#define NN   50000
#define EE   150000
#define DD   256
#define NP   768          // P columns = 3 * 256
#define SCAN_BLOCKS 49    // ceil(50000/1024)
#define NSLICE 4

// ------------------------ device scratch (no allocs allowed) ------------------
__device__ int   g_deg [3 * NN];
__device__ int   g_cur [3 * NN];
__device__ int   g_rs  [3 * (NN + 1)];
__device__ int   g_bsum[3 * SCAN_BLOCKS];
__device__ int   g_boff[3 * SCAN_BLOCKS];
__device__ int   g_snbr[3 * 2 * EE];

__device__ __half g_Sh [(size_t)NN * DD];
__device__ __half g_Wah[(size_t)NP * DD];   // [n=r*256+d][k]
__device__ __half g_Wvh[(size_t)DD * NP];   // [n=d][k'=r*256+k]
__device__ float  g_P  [(size_t)NN * NP];   // 153.6 MB
__device__ __half g_Th [(size_t)NN * NP];

// ------------------------ PTX helpers ----------------------------------------
__device__ __forceinline__ uint32_t smem_u32(const void* p) {
    return (uint32_t)__cvta_generic_to_shared(p);
}
__device__ __forceinline__ void cp16(uint32_t dst, const void* src, int srcsz) {
    asm volatile("cp.async.cg.shared.global [%0], [%1], 16, %2;"
                 :: "r"(dst), "l"(src), "r"(srcsz) : "memory");
}
#define CP_COMMIT() asm volatile("cp.async.commit_group;" ::: "memory")
#define CP_WAIT(n)  asm volatile("cp.async.wait_group %0;" :: "n"(n) : "memory")

#define LDSM4(r, addr) asm volatile( \
    "ldmatrix.sync.aligned.m8n8.x4.shared.b16 {%0,%1,%2,%3}, [%4];" \
    : "=r"((r)[0]), "=r"((r)[1]), "=r"((r)[2]), "=r"((r)[3]) : "r"(addr))

#define MMA16816H(d, a, b) asm volatile( \
    "mma.sync.aligned.m16n8k16.row.col.f32.f16.f16.f32 " \
    "{%0,%1,%2,%3}, {%4,%5,%6,%7}, {%8,%9}, {%0,%1,%2,%3};" \
    : "+f"((d)[0]), "+f"((d)[1]), "+f"((d)[2]), "+f"((d)[3]) \
    : "r"((a)[0]), "r"((a)[1]), "r"((a)[2]), "r"((a)[3]), \
      "r"((b)[0]), "r"((b)[1]))

// ------------------------ CSR build ------------------------------------------
__global__ void zero_kernel() {
    int idx = blockIdx.x * blockDim.x + threadIdx.x;
    if (idx < 3 * NN) { g_deg[idx] = 0; g_cur[idx] = 0; }
}

__global__ void degree_kernel(const int* __restrict__ e0,
                              const int* __restrict__ e1,
                              const int* __restrict__ e2) {
    int idx = blockIdx.x * blockDim.x + threadIdx.x;
    if (idx >= 3 * 2 * EE) return;
    int r = idx / (2 * EE);
    int k = idx - r * (2 * EE);
    const int* e = (r == 0) ? e0 : ((r == 1) ? e1 : e2);
    atomicAdd(&g_deg[r * NN + e[k]], 1);
}

__global__ void scan_local() {
    __shared__ int buf[1024];
    int r = blockIdx.y;
    int tid = threadIdx.x;
    int idx = blockIdx.x * 1024 + tid;
    int v = (idx < NN) ? g_deg[r * NN + idx] : 0;
    buf[tid] = v;
    __syncthreads();
    for (int off = 1; off < 1024; off <<= 1) {
        int t = (tid >= off) ? buf[tid - off] : 0;
        __syncthreads();
        buf[tid] += t;
        __syncthreads();
    }
    if (idx < NN) g_rs[r * (NN + 1) + idx] = buf[tid] - v;
    if (tid == 1023) g_bsum[r * SCAN_BLOCKS + blockIdx.x] = buf[1023];
}

__global__ void scan_bsums() {
    int r = threadIdx.x >> 5;
    int lane = threadIdx.x & 31;
    if (r >= 3) return;
    int carry = 0;
    for (int b0 = 0; b0 < SCAN_BLOCKS; b0 += 32) {
        int idx = b0 + lane;
        int orig = (idx < SCAN_BLOCKS) ? g_bsum[r * SCAN_BLOCKS + idx] : 0;
        int v = orig;
#pragma unroll
        for (int off = 1; off < 32; off <<= 1) {
            int t = __shfl_up_sync(0xFFFFFFFFu, v, off);
            if (lane >= off) v += t;
        }
        if (idx < SCAN_BLOCKS) g_boff[r * SCAN_BLOCKS + idx] = carry + v - orig;
        carry += __shfl_sync(0xFFFFFFFFu, v, 31);
    }
    if (lane == 0) g_rs[r * (NN + 1) + NN] = carry;
}

__global__ void scan_add() {
    int r = blockIdx.y;
    int idx = blockIdx.x * 1024 + threadIdx.x;
    if (idx < NN) g_rs[r * (NN + 1) + idx] += g_boff[r * SCAN_BLOCKS + blockIdx.x];
}

__global__ void fill_kernel(const int* __restrict__ e0,
                            const int* __restrict__ e1,
                            const int* __restrict__ e2) {
    int idx = blockIdx.x * blockDim.x + threadIdx.x;
    if (idx >= 3 * EE) return;
    int r = idx / EE;
    int k = idx - r * EE;
    const int* e = (r == 0) ? e0 : ((r == 1) ? e1 : e2);
    int a = e[2 * k], b = e[2 * k + 1];
    int pa = g_rs[r * (NN + 1) + a] + atomicAdd(&g_cur[r * NN + a], 1);
    g_snbr[r * 2 * EE + pa] = b;
    int pb = g_rs[r * (NN + 1) + b] + atomicAdd(&g_cur[r * NN + b], 1);
    g_snbr[r * 2 * EE + pb] = a;
}

// ------------------------ conversions ----------------------------------------
__device__ __forceinline__ void cvt4h(float4 v, __half* hp) {
    ((__half2*)hp)[0] = __halves2half2(__float2half(v.x), __float2half(v.y));
    ((__half2*)hp)[1] = __halves2half2(__float2half(v.z), __float2half(v.w));
}

__global__ void convertS_kernel(const float* __restrict__ S) {
    int idx = blockIdx.x * blockDim.x + threadIdx.x;      // float4 index
    if (idx >= NN * DD / 4) return;
    float4 v = ((const float4*)S)[idx];
    cvt4h(v, g_Sh + idx * 4);
}

// Wa[n=r*256+d][k] = A_r[k][d] = sum_j WQ_r[j][k] * WK_r[j][d]
__global__ void build_wa(const float* __restrict__ WQ,
                         const float* __restrict__ WK) {
    int b = blockIdx.x;            // 0..767
    int r = b >> 8;
    int k = b & 255;
    int d = threadIdx.x;           // 0..255
    const float* wq = WQ + r * 65536;
    const float* wk = WK + r * 65536;
    float acc = 0.f;
#pragma unroll 8
    for (int j = 0; j < 256; j++)
        acc += wq[j * 256 + k] * wk[j * 256 + d];
    g_Wah[(size_t)(r * 256 + d) * DD + k] = __float2half(acc);
}

// Wv[n=d][k'=r*256+k] = W_r[d][k]
__global__ void build_wv(const float* __restrict__ W) {
    int idx = blockIdx.x * blockDim.x + threadIdx.x;
    if (idx >= DD * NP) return;
    int d  = idx / NP;
    int rk = idx - d * NP;
    int r  = rk >> 8;
    int k  = rk & 255;
    g_Wvh[idx] = __float2half(W[r * 65536 + d * 256 + k]);
}

// ------------------------ mma.sync fp16 single-product GEMM ------------------
// C = A @ B^T, fp16 inputs, fp32 accum. BM=128, BN=128, BK=64, 256 threads
// (2x4 warps, warp tile 64x32), 3-stage cp.async pipeline, SW128-style swizzle.
#define STG      32768
#define GEMM_SMEM (3 * STG)

__global__ void __launch_bounds__(256)
mma_gemm(const __half* __restrict__ A, const __half* __restrict__ B,
         float* __restrict__ C, int mbase, int mEnd, int K, int N, int relu) {
    extern __shared__ char smem[];
    const uint32_t sbase = smem_u32(smem);
    const int t = threadIdx.x;
    const int w = t >> 5, l = t & 31;
    const int wm = (w >> 2) * 64;
    const int wn = (w & 3) * 32;
    const int bm = mbase + blockIdx.y * 128;
    const int n0 = blockIdx.x * 128;

    const int lrow = t >> 1;
    const int half = t & 1;
    int mrow = bm + lrow;
    int av = (mrow < mEnd) ? 16 : 0;
    const __half* aRow = A + (size_t)((mrow < mEnd) ? mrow : 0) * K;
    const __half* bRow = B + (size_t)(n0 + lrow) * K;
    const uint32_t aDst = sbase + lrow * 128;
    const uint32_t bDst = sbase + 16384 + lrow * 128;

    float acc[4][4][4];
#pragma unroll
    for (int i = 0; i < 4; i++)
#pragma unroll
        for (int j = 0; j < 4; j++)
#pragma unroll
            for (int q = 0; q < 4; q++) acc[i][j][q] = 0.f;

    auto load_stage = [&](int s, int kt) {
        uint32_t so = (uint32_t)s * STG;
#pragma unroll
        for (int c = 0; c < 4; c++) {
            int chunk = half * 4 + c;
            uint32_t sw = (uint32_t)((chunk ^ (lrow & 7)) << 4);
            cp16(aDst + so + sw, aRow + kt * 64 + chunk * 8, av);
            cp16(bDst + so + sw, bRow + kt * 64 + chunk * 8, 16);
        }
    };

    auto compute = [&](int s) {
        uint32_t aB = sbase + (uint32_t)s * STG;
        uint32_t bB = aB + 16384;
#pragma unroll
        for (int ks = 0; ks < 4; ks++) {
            uint32_t Af[4][4];
#pragma unroll
            for (int im = 0; im < 4; im++) {
                int row = wm + im * 16 + (l & 15);
                int ch = ks * 2 + (l >> 4);
                LDSM4(Af[im], aB + row * 128 + ((ch ^ (row & 7)) << 4));
            }
            uint32_t Bf[4][2];
#pragma unroll
            for (int p = 0; p < 2; p++) {
                int row = wn + p * 16 + (l & 7) + ((l >> 4) & 1) * 8;
                int ch = ks * 2 + ((l >> 3) & 1);
                uint32_t r4[4];
                LDSM4(r4, bB + row * 128 + ((ch ^ (row & 7)) << 4));
                Bf[p * 2][0] = r4[0]; Bf[p * 2][1] = r4[1];
                Bf[p * 2 + 1][0] = r4[2]; Bf[p * 2 + 1][1] = r4[3];
            }
#pragma unroll
            for (int im = 0; im < 4; im++)
#pragma unroll
                for (int in = 0; in < 4; in++)
                    MMA16816H(acc[im][in], Af[im], Bf[in]);
        }
    };

    const int KT = K / 64;
    load_stage(0, 0); CP_COMMIT();
    load_stage(1, 1); CP_COMMIT();
    int s = 0;
    for (int kt = 0; kt < KT; kt++) {
        if (kt < KT - 1) { CP_WAIT(1); } else { CP_WAIT(0); }
        __syncthreads();
        if (kt + 2 < KT) {
            int s2 = s + 2; if (s2 >= 3) s2 -= 3;
            load_stage(s2, kt + 2);
            CP_COMMIT();
        }
        compute(s);
        if (++s == 3) s = 0;
    }

#pragma unroll
    for (int im = 0; im < 4; im++) {
        int r0 = bm + wm + im * 16 + (l >> 2);
#pragma unroll
        for (int in = 0; in < 4; in++) {
            int cc = n0 + wn + in * 8 + (l & 3) * 2;
            float* a4 = acc[im][in];
            if (relu) {
                a4[0] = fmaxf(a4[0], 0.f); a4[1] = fmaxf(a4[1], 0.f);
                a4[2] = fmaxf(a4[2], 0.f); a4[3] = fmaxf(a4[3], 0.f);
            }
            if (r0 < mEnd)
                *(float2*)(C + (size_t)r0 * N + cc) = make_float2(a4[0], a4[1]);
            if (r0 + 8 < mEnd)
                *(float2*)(C + (size_t)(r0 + 8) * N + cc) = make_float2(a4[2], a4[3]);
        }
    }
}

// ------------------------ fused attention aggregation (fp16 gathers) ---------
// Warp per node; lane l owns elements 8l..8l+7 (one 16B fp16 load per edge).
__global__ __launch_bounds__(256)
void agg_kernel(int nbase, int nEnd) {
    int w = threadIdx.x >> 5;
    int l = threadIdx.x & 31;
    int i = nbase + blockIdx.x * 8 + w;
    if (i >= nEnd) return;

    for (int r = 0; r < 3; r++) {
        float acc[8];
#pragma unroll
        for (int q = 0; q < 8; q++) acc[q] = 0.f;
        int start = g_rs[r * (NN + 1) + i];
        int deg   = g_rs[r * (NN + 1) + i + 1] - start;

        if (deg > 0) {
            const float* Pb = g_P + (size_t)i * NP + r * 256 + 8 * l;
            float4 p0 = *(const float4*)(Pb);
            float4 p1 = *(const float4*)(Pb + 4);
            float p[8] = {p0.x, p0.y, p0.z, p0.w, p1.x, p1.y, p1.z, p1.w};
            const int* nb = g_snbr + r * 2 * EE + start;

            float z = 0.f;
            for (int j = 0; j < deg; j++) {
                int nbr = nb[j];
                uint4 raw = *(const uint4*)(g_Sh + (size_t)nbr * DD + 8 * l);
                __half2 h01 = *(__half2*)&raw.x;
                __half2 h23 = *(__half2*)&raw.y;
                __half2 h45 = *(__half2*)&raw.z;
                __half2 h67 = *(__half2*)&raw.w;
                float sv[8];
                float2 f;
                f = __half22float2(h01); sv[0] = f.x; sv[1] = f.y;
                f = __half22float2(h23); sv[2] = f.x; sv[3] = f.y;
                f = __half22float2(h45); sv[4] = f.x; sv[5] = f.y;
                f = __half22float2(h67); sv[6] = f.x; sv[7] = f.y;
                float d = 0.f;
#pragma unroll
                for (int q = 0; q < 8; q++) d += p[q] * sv[q];
#pragma unroll
                for (int off = 16; off; off >>= 1)
                    d += __shfl_xor_sync(0xFFFFFFFFu, d, off);
                float e = __expf(d * 0.125f);
                z += e;
#pragma unroll
                for (int q = 0; q < 8; q++) acc[q] += e * sv[q];
            }
            float zi = 1.f / z;
#pragma unroll
            for (int q = 0; q < 8; q++) acc[q] *= zi;
        }
        __half* tp = g_Th + (size_t)i * NP + r * 256 + 8 * l;
        cvt4h(make_float4(acc[0], acc[1], acc[2], acc[3]), tp);
        cvt4h(make_float4(acc[4], acc[5], acc[6], acc[7]), tp + 4);
    }
}

// ------------------------ launch --------------------------------------------
extern "C" void kernel_launch(void* const* d_in, const int* in_sizes, int n_in,
                              void* d_out, int out_size) {
    const float* S  = (const float*)d_in[0];
    const int*   et = (const int*)d_in[1];
    const int*   ec = (const int*)d_in[2];
    const int*   e2 = (const int*)d_in[3];
    const float* W  = (const float*)d_in[4];
    const float* WQ = (const float*)d_in[5];
    const float* WK = (const float*)d_in[6];
    float* out = (float*)d_out;

    static bool init = false;
    static __half *pSh, *pWah, *pWvh, *pTh;
    static float* pP;
    static cudaStream_t s1, s2, s3;
    static cudaEvent_t evFork, evCSR, evW;
    static cudaEvent_t evG1[NSLICE], evA[NSLICE];
    if (!init) {
        cudaGetSymbolAddress((void**)&pSh,  g_Sh);
        cudaGetSymbolAddress((void**)&pWah, g_Wah);
        cudaGetSymbolAddress((void**)&pWvh, g_Wvh);
        cudaGetSymbolAddress((void**)&pTh,  g_Th);
        cudaGetSymbolAddress((void**)&pP,   g_P);
        cudaFuncSetAttribute(mma_gemm, cudaFuncAttributeMaxDynamicSharedMemorySize,
                             GEMM_SMEM);
        cudaStreamCreateWithFlags(&s1, cudaStreamNonBlocking);
        cudaStreamCreateWithFlags(&s2, cudaStreamNonBlocking);
        cudaStreamCreateWithFlags(&s3, cudaStreamNonBlocking);
        cudaEventCreateWithFlags(&evFork, cudaEventDisableTiming);
        cudaEventCreateWithFlags(&evCSR,  cudaEventDisableTiming);
        cudaEventCreateWithFlags(&evW,    cudaEventDisableTiming);
        for (int i = 0; i < NSLICE; i++) {
            cudaEventCreateWithFlags(&evG1[i], cudaEventDisableTiming);
            cudaEventCreateWithFlags(&evA[i],  cudaEventDisableTiming);
        }
        init = true;
    }

    static const int SB[NSLICE + 1] = {0, 12544, 25088, 37632, NN};

    // fork
    cudaEventRecord(evFork, 0);
    cudaStreamWaitEvent(s1, evFork, 0);
    cudaStreamWaitEvent(s2, evFork, 0);
    cudaStreamWaitEvent(s3, evFork, 0);

    // s1: CSR build chain
    zero_kernel<<<(3 * NN + 255) / 256, 256, 0, s1>>>();
    degree_kernel<<<(3 * 2 * EE + 255) / 256, 256, 0, s1>>>(et, ec, e2);
    scan_local<<<dim3(SCAN_BLOCKS, 3), 1024, 0, s1>>>();
    scan_bsums<<<1, 96, 0, s1>>>();
    scan_add<<<dim3(SCAN_BLOCKS, 3), 1024, 0, s1>>>();
    fill_kernel<<<(3 * EE + 255) / 256, 256, 0, s1>>>(et, ec, e2);
    cudaEventRecord(evCSR, s1);

    // s2: weight prep
    build_wa<<<NP, 256, 0, s2>>>(WQ, WK);
    build_wv<<<(DD * NP + 255) / 256, 256, 0, s2>>>(W);
    cudaEventRecord(evW, s2);

    // main: convert S, then GEMM1 slices
    convertS_kernel<<<(NN * DD / 4 + 255) / 256, 256>>>(S);
    cudaStreamWaitEvent(0, evW, 0);
    for (int i = 0; i < NSLICE; i++) {
        int mb = (SB[i + 1] - SB[i] + 127) / 128;
        mma_gemm<<<dim3(NP / 128, mb), 256, GEMM_SMEM>>>(
            pSh, pWah, pP, SB[i], SB[i + 1], DD, NP, 0);
        cudaEventRecord(evG1[i], 0);
    }

    // s3: agg slices pipelined behind GEMM1 slices
    cudaStreamWaitEvent(s3, evCSR, 0);
    for (int i = 0; i < NSLICE; i++) {
        cudaStreamWaitEvent(s3, evG1[i], 0);
        int nb = (SB[i + 1] - SB[i] + 7) / 8;
        agg_kernel<<<nb, 256, 0, s3>>>(SB[i], SB[i + 1]);
        cudaEventRecord(evA[i], s3);
    }

    // main: GEMM2 slices (relu fused), each gated on its agg slice
    for (int i = 0; i < NSLICE; i++) {
        cudaStreamWaitEvent(0, evA[i], 0);
        int mb = (SB[i + 1] - SB[i] + 127) / 128;
        mma_gemm<<<dim3(DD / 128, mb), 256, GEMM_SMEM>>>(
            pTh, pWvh, out, SB[i], SB[i + 1], NP, DD, 1);
    }
}

// round 15
// speedup vs baseline: 1.0716x; 1.0716x over previous
#include <cuda_runtime.h>
#include <cuda_fp16.h>
#include <math.h>
#include <stdint.h>

#define NN   50000
#define EE   150000
#define DD   256
#define NP   768          // P columns = 3 * 256
#define SCAN_BLOCKS 49    // ceil(50000/1024)
#define MSPLIT 25088      // 196 * 128

// ------------------------ device scratch (no allocs allowed) ------------------
__device__ int   g_deg [3 * NN];
__device__ int   g_cur [3 * NN];
__device__ int   g_rs  [3 * (NN + 1)];
__device__ int   g_bsum[3 * SCAN_BLOCKS];
__device__ int   g_boff[3 * SCAN_BLOCKS];
__device__ int   g_snbr[3 * 2 * EE];

__device__ __half g_Sh [(size_t)NN * DD];
__device__ __half g_Wah[(size_t)NP * DD];   // [n=r*256+d][k]
__device__ __half g_Wvh[(size_t)DD * NP];   // [n=d][k'=r*256+k]
__device__ float  g_P  [(size_t)NN * NP];   // 153.6 MB
__device__ __half g_Th [(size_t)NN * NP];

// ------------------------ PTX helpers ----------------------------------------
__device__ __forceinline__ uint32_t smem_u32(const void* p) {
    return (uint32_t)__cvta_generic_to_shared(p);
}
__device__ __forceinline__ void cp16(uint32_t dst, const void* src, int srcsz) {
    asm volatile("cp.async.cg.shared.global [%0], [%1], 16, %2;"
                 :: "r"(dst), "l"(src), "r"(srcsz) : "memory");
}
#define CP_COMMIT() asm volatile("cp.async.commit_group;" ::: "memory")
#define CP_WAIT(n)  asm volatile("cp.async.wait_group %0;" :: "n"(n) : "memory")

#define LDSM4(r, addr) asm volatile( \
    "ldmatrix.sync.aligned.m8n8.x4.shared.b16 {%0,%1,%2,%3}, [%4];" \
    : "=r"((r)[0]), "=r"((r)[1]), "=r"((r)[2]), "=r"((r)[3]) : "r"(addr))

#define MMA16816H(d, a, b) asm volatile( \
    "mma.sync.aligned.m16n8k16.row.col.f32.f16.f16.f32 " \
    "{%0,%1,%2,%3}, {%4,%5,%6,%7}, {%8,%9}, {%0,%1,%2,%3};" \
    : "+f"((d)[0]), "+f"((d)[1]), "+f"((d)[2]), "+f"((d)[3]) \
    : "r"((a)[0]), "r"((a)[1]), "r"((a)[2]), "r"((a)[3]), \
      "r"((b)[0]), "r"((b)[1]))

// ------------------------ CSR build ------------------------------------------
__global__ void zero_kernel() {
    int idx = blockIdx.x * blockDim.x + threadIdx.x;
    if (idx < 3 * NN) { g_deg[idx] = 0; g_cur[idx] = 0; }
}

__global__ void degree_kernel(const int* __restrict__ e0,
                              const int* __restrict__ e1,
                              const int* __restrict__ e2) {
    int idx = blockIdx.x * blockDim.x + threadIdx.x;
    if (idx >= 3 * 2 * EE) return;
    int r = idx / (2 * EE);
    int k = idx - r * (2 * EE);
    const int* e = (r == 0) ? e0 : ((r == 1) ? e1 : e2);
    atomicAdd(&g_deg[r * NN + e[k]], 1);
}

__global__ void scan_local() {
    __shared__ int buf[1024];
    int r = blockIdx.y;
    int tid = threadIdx.x;
    int idx = blockIdx.x * 1024 + tid;
    int v = (idx < NN) ? g_deg[r * NN + idx] : 0;
    buf[tid] = v;
    __syncthreads();
    for (int off = 1; off < 1024; off <<= 1) {
        int t = (tid >= off) ? buf[tid - off] : 0;
        __syncthreads();
        buf[tid] += t;
        __syncthreads();
    }
    if (idx < NN) g_rs[r * (NN + 1) + idx] = buf[tid] - v;
    if (tid == 1023) g_bsum[r * SCAN_BLOCKS + blockIdx.x] = buf[1023];
}

__global__ void scan_bsums() {
    int r = threadIdx.x >> 5;
    int lane = threadIdx.x & 31;
    if (r >= 3) return;
    int carry = 0;
    for (int b0 = 0; b0 < SCAN_BLOCKS; b0 += 32) {
        int idx = b0 + lane;
        int orig = (idx < SCAN_BLOCKS) ? g_bsum[r * SCAN_BLOCKS + idx] : 0;
        int v = orig;
#pragma unroll
        for (int off = 1; off < 32; off <<= 1) {
            int t = __shfl_up_sync(0xFFFFFFFFu, v, off);
            if (lane >= off) v += t;
        }
        if (idx < SCAN_BLOCKS) g_boff[r * SCAN_BLOCKS + idx] = carry + v - orig;
        carry += __shfl_sync(0xFFFFFFFFu, v, 31);
    }
    if (lane == 0) g_rs[r * (NN + 1) + NN] = carry;
}

__global__ void scan_add() {
    int r = blockIdx.y;
    int idx = blockIdx.x * 1024 + threadIdx.x;
    if (idx < NN) g_rs[r * (NN + 1) + idx] += g_boff[r * SCAN_BLOCKS + blockIdx.x];
}

__global__ void fill_kernel(const int* __restrict__ e0,
                            const int* __restrict__ e1,
                            const int* __restrict__ e2) {
    int idx = blockIdx.x * blockDim.x + threadIdx.x;
    if (idx >= 3 * EE) return;
    int r = idx / EE;
    int k = idx - r * EE;
    const int* e = (r == 0) ? e0 : ((r == 1) ? e1 : e2);
    int a = e[2 * k], b = e[2 * k + 1];
    int pa = g_rs[r * (NN + 1) + a] + atomicAdd(&g_cur[r * NN + a], 1);
    g_snbr[r * 2 * EE + pa] = b;
    int pb = g_rs[r * (NN + 1) + b] + atomicAdd(&g_cur[r * NN + b], 1);
    g_snbr[r * 2 * EE + pb] = a;
}

// ------------------------ conversions ----------------------------------------
__device__ __forceinline__ void cvt4h(float4 v, __half* hp) {
    ((__half2*)hp)[0] = __halves2half2(__float2half(v.x), __float2half(v.y));
    ((__half2*)hp)[1] = __halves2half2(__float2half(v.z), __float2half(v.w));
}

__global__ void convertS_kernel(const float* __restrict__ S) {
    int idx = blockIdx.x * blockDim.x + threadIdx.x;      // float4 index
    if (idx >= NN * DD / 4) return;
    float4 v = ((const float4*)S)[idx];
    cvt4h(v, g_Sh + idx * 4);
}

// Wa[n=r*256+d][k] = A_r[k][d] = sum_j WQ_r[j][k] * WK_r[j][d]
__global__ void build_wa(const float* __restrict__ WQ,
                         const float* __restrict__ WK) {
    int b = blockIdx.x;            // 0..767
    int r = b >> 8;
    int k = b & 255;
    int d = threadIdx.x;           // 0..255
    const float* wq = WQ + r * 65536;
    const float* wk = WK + r * 65536;
    float acc = 0.f;
#pragma unroll 8
    for (int j = 0; j < 256; j++)
        acc += wq[j * 256 + k] * wk[j * 256 + d];
    g_Wah[(size_t)(r * 256 + d) * DD + k] = __float2half(acc);
}

// Wv[n=d][k'=r*256+k] = W_r[d][k]
__global__ void build_wv(const float* __restrict__ W) {
    int idx = blockIdx.x * blockDim.x + threadIdx.x;
    if (idx >= DD * NP) return;
    int d  = idx / NP;
    int rk = idx - d * NP;
    int r  = rk >> 8;
    int k  = rk & 255;
    g_Wvh[idx] = __float2half(W[r * 65536 + d * 256 + k]);
}

// ------------------------ mma.sync fp16 single-product GEMM ------------------
// C = A @ B^T, fp16 inputs, fp32 accum. BM=128, BN=128, BK=64, 256 threads
// (2x4 warps, warp tile 64x32), 3-stage cp.async pipeline, SW128-style swizzle.
#define STG      32768
#define GEMM_SMEM (3 * STG)

__global__ void __launch_bounds__(256)
mma_gemm(const __half* __restrict__ A, const __half* __restrict__ B,
         float* __restrict__ C, int mbase, int mEnd, int K, int N, int relu) {
    extern __shared__ char smem[];
    const uint32_t sbase = smem_u32(smem);
    const int t = threadIdx.x;
    const int w = t >> 5, l = t & 31;
    const int wm = (w >> 2) * 64;
    const int wn = (w & 3) * 32;
    const int bm = mbase + blockIdx.y * 128;
    const int n0 = blockIdx.x * 128;

    const int lrow = t >> 1;
    const int half = t & 1;
    int mrow = bm + lrow;
    int av = (mrow < mEnd) ? 16 : 0;
    const __half* aRow = A + (size_t)((mrow < mEnd) ? mrow : 0) * K;
    const __half* bRow = B + (size_t)(n0 + lrow) * K;
    const uint32_t aDst = sbase + lrow * 128;
    const uint32_t bDst = sbase + 16384 + lrow * 128;

    float acc[4][4][4];
#pragma unroll
    for (int i = 0; i < 4; i++)
#pragma unroll
        for (int j = 0; j < 4; j++)
#pragma unroll
            for (int q = 0; q < 4; q++) acc[i][j][q] = 0.f;

    auto load_stage = [&](int s, int kt) {
        uint32_t so = (uint32_t)s * STG;
#pragma unroll
        for (int c = 0; c < 4; c++) {
            int chunk = half * 4 + c;
            uint32_t sw = (uint32_t)((chunk ^ (lrow & 7)) << 4);
            cp16(aDst + so + sw, aRow + kt * 64 + chunk * 8, av);
            cp16(bDst + so + sw, bRow + kt * 64 + chunk * 8, 16);
        }
    };

    auto compute = [&](int s) {
        uint32_t aB = sbase + (uint32_t)s * STG;
        uint32_t bB = aB + 16384;
#pragma unroll
        for (int ks = 0; ks < 4; ks++) {
            uint32_t Af[4][4];
#pragma unroll
            for (int im = 0; im < 4; im++) {
                int row = wm + im * 16 + (l & 15);
                int ch = ks * 2 + (l >> 4);
                LDSM4(Af[im], aB + row * 128 + ((ch ^ (row & 7)) << 4));
            }
            uint32_t Bf[4][2];
#pragma unroll
            for (int p = 0; p < 2; p++) {
                int row = wn + p * 16 + (l & 7) + ((l >> 4) & 1) * 8;
                int ch = ks * 2 + ((l >> 3) & 1);
                uint32_t r4[4];
                LDSM4(r4, bB + row * 128 + ((ch ^ (row & 7)) << 4));
                Bf[p * 2][0] = r4[0]; Bf[p * 2][1] = r4[1];
                Bf[p * 2 + 1][0] = r4[2]; Bf[p * 2 + 1][1] = r4[3];
            }
#pragma unroll
            for (int im = 0; im < 4; im++)
#pragma unroll
                for (int in = 0; in < 4; in++)
                    MMA16816H(acc[im][in], Af[im], Bf[in]);
        }
    };

    const int KT = K / 64;
    load_stage(0, 0); CP_COMMIT();
    load_stage(1, 1); CP_COMMIT();
    int s = 0;
    for (int kt = 0; kt < KT; kt++) {
        if (kt < KT - 1) { CP_WAIT(1); } else { CP_WAIT(0); }
        __syncthreads();
        if (kt + 2 < KT) {
            int s2 = s + 2; if (s2 >= 3) s2 -= 3;
            load_stage(s2, kt + 2);
            CP_COMMIT();
        }
        compute(s);
        if (++s == 3) s = 0;
    }

#pragma unroll
    for (int im = 0; im < 4; im++) {
        int r0 = bm + wm + im * 16 + (l >> 2);
#pragma unroll
        for (int in = 0; in < 4; in++) {
            int cc = n0 + wn + in * 8 + (l & 3) * 2;
            float* a4 = acc[im][in];
            if (relu) {
                a4[0] = fmaxf(a4[0], 0.f); a4[1] = fmaxf(a4[1], 0.f);
                a4[2] = fmaxf(a4[2], 0.f); a4[3] = fmaxf(a4[3], 0.f);
            }
            if (r0 < mEnd)
                *(float2*)(C + (size_t)r0 * N + cc) = make_float2(a4[0], a4[1]);
            if (r0 + 8 < mEnd)
                *(float2*)(C + (size_t)(r0 + 8) * N + cc) = make_float2(a4[2], a4[3]);
        }
    }
}

// ------------------------ fused attention aggregation (fp16 gathers) ---------
// Warp per node; lane l owns elements 8l..8l+7 (one 16B fp16 load per edge).
__global__ __launch_bounds__(256)
void agg_kernel(int nbase, int nEnd) {
    int w = threadIdx.x >> 5;
    int l = threadIdx.x & 31;
    int i = nbase + blockIdx.x * 8 + w;
    if (i >= nEnd) return;

    for (int r = 0; r < 3; r++) {
        float acc[8];
#pragma unroll
        for (int q = 0; q < 8; q++) acc[q] = 0.f;
        int start = g_rs[r * (NN + 1) + i];
        int deg   = g_rs[r * (NN + 1) + i + 1] - start;

        if (deg > 0) {
            const float* Pb = g_P + (size_t)i * NP + r * 256 + 8 * l;
            float4 p0 = *(const float4*)(Pb);
            float4 p1 = *(const float4*)(Pb + 4);
            float p[8] = {p0.x, p0.y, p0.z, p0.w, p1.x, p1.y, p1.z, p1.w};
            const int* nb = g_snbr + r * 2 * EE + start;

            float z = 0.f;
            for (int j = 0; j < deg; j++) {
                int nbr = nb[j];
                uint4 raw = *(const uint4*)(g_Sh + (size_t)nbr * DD + 8 * l);
                float sv[8];
                float2 f;
                f = __half22float2(*(__half2*)&raw.x); sv[0] = f.x; sv[1] = f.y;
                f = __half22float2(*(__half2*)&raw.y); sv[2] = f.x; sv[3] = f.y;
                f = __half22float2(*(__half2*)&raw.z); sv[4] = f.x; sv[5] = f.y;
                f = __half22float2(*(__half2*)&raw.w); sv[6] = f.x; sv[7] = f.y;
                float d = 0.f;
#pragma unroll
                for (int q = 0; q < 8; q++) d += p[q] * sv[q];
#pragma unroll
                for (int off = 16; off; off >>= 1)
                    d += __shfl_xor_sync(0xFFFFFFFFu, d, off);
                float e = __expf(d * 0.125f);
                z += e;
#pragma unroll
                for (int q = 0; q < 8; q++) acc[q] += e * sv[q];
            }
            float zi = 1.f / z;
#pragma unroll
            for (int q = 0; q < 8; q++) acc[q] *= zi;
        }
        __half* tp = g_Th + (size_t)i * NP + r * 256 + 8 * l;
        cvt4h(make_float4(acc[0], acc[1], acc[2], acc[3]), tp);
        cvt4h(make_float4(acc[4], acc[5], acc[6], acc[7]), tp + 4);
    }
}

// ------------------------ launch --------------------------------------------
extern "C" void kernel_launch(void* const* d_in, const int* in_sizes, int n_in,
                              void* d_out, int out_size) {
    const float* S  = (const float*)d_in[0];
    const int*   et = (const int*)d_in[1];
    const int*   ec = (const int*)d_in[2];
    const int*   e2 = (const int*)d_in[3];
    const float* W  = (const float*)d_in[4];
    const float* WQ = (const float*)d_in[5];
    const float* WK = (const float*)d_in[6];
    float* out = (float*)d_out;

    static bool init = false;
    static __half *pSh, *pWah, *pWvh, *pTh;
    static float* pP;
    static cudaStream_t s1, s2, s3;
    static cudaEvent_t evFork, evCSR, evW, evG1a, evG1b, evAa, evAb;
    if (!init) {
        cudaGetSymbolAddress((void**)&pSh,  g_Sh);
        cudaGetSymbolAddress((void**)&pWah, g_Wah);
        cudaGetSymbolAddress((void**)&pWvh, g_Wvh);
        cudaGetSymbolAddress((void**)&pTh,  g_Th);
        cudaGetSymbolAddress((void**)&pP,   g_P);
        cudaFuncSetAttribute(mma_gemm, cudaFuncAttributeMaxDynamicSharedMemorySize,
                             GEMM_SMEM);
        int loPri, hiPri;
        cudaDeviceGetStreamPriorityRange(&loPri, &hiPri);
        cudaStreamCreateWithFlags(&s1, cudaStreamNonBlocking);
        cudaStreamCreateWithFlags(&s2, cudaStreamNonBlocking);
        cudaStreamCreateWithPriority(&s3, cudaStreamNonBlocking, hiPri);
        cudaEventCreateWithFlags(&evFork, cudaEventDisableTiming);
        cudaEventCreateWithFlags(&evCSR,  cudaEventDisableTiming);
        cudaEventCreateWithFlags(&evW,    cudaEventDisableTiming);
        cudaEventCreateWithFlags(&evG1a,  cudaEventDisableTiming);
        cudaEventCreateWithFlags(&evG1b,  cudaEventDisableTiming);
        cudaEventCreateWithFlags(&evAa,   cudaEventDisableTiming);
        cudaEventCreateWithFlags(&evAb,   cudaEventDisableTiming);
        init = true;
    }

    const int MB_A = MSPLIT / 128;                 // 196
    const int MB_B = (NN - MSPLIT + 127) / 128;    // 195
    const int NB_A = (MSPLIT + 7) / 8;
    const int NB_B = (NN - MSPLIT + 7) / 8;

    // fork
    cudaEventRecord(evFork, 0);
    cudaStreamWaitEvent(s1, evFork, 0);
    cudaStreamWaitEvent(s2, evFork, 0);
    cudaStreamWaitEvent(s3, evFork, 0);

    // s1: CSR build chain
    zero_kernel<<<(3 * NN + 255) / 256, 256, 0, s1>>>();
    degree_kernel<<<(3 * 2 * EE + 255) / 256, 256, 0, s1>>>(et, ec, e2);
    scan_local<<<dim3(SCAN_BLOCKS, 3), 1024, 0, s1>>>();
    scan_bsums<<<1, 96, 0, s1>>>();
    scan_add<<<dim3(SCAN_BLOCKS, 3), 1024, 0, s1>>>();
    fill_kernel<<<(3 * EE + 255) / 256, 256, 0, s1>>>(et, ec, e2);
    cudaEventRecord(evCSR, s1);

    // s2: weight prep
    build_wa<<<NP, 256, 0, s2>>>(WQ, WK);
    build_wv<<<(DD * NP + 255) / 256, 256, 0, s2>>>(W);
    cudaEventRecord(evW, s2);

    // main: convert S, then GEMM1 in two M-slices
    convertS_kernel<<<(NN * DD / 4 + 255) / 256, 256>>>(S);
    cudaStreamWaitEvent(0, evW, 0);
    mma_gemm<<<dim3(NP / 128, MB_A), 256, GEMM_SMEM>>>(
        pSh, pWah, pP, 0, MSPLIT, DD, NP, 0);
    cudaEventRecord(evG1a, 0);
    mma_gemm<<<dim3(NP / 128, MB_B), 256, GEMM_SMEM>>>(
        pSh, pWah, pP, MSPLIT, NN, DD, NP, 0);
    cudaEventRecord(evG1b, 0);

    // s3: agg slices (overlap with GEMM1b / GEMM2a); high-priority stream
    cudaStreamWaitEvent(s3, evCSR, 0);
    cudaStreamWaitEvent(s3, evG1a, 0);
    agg_kernel<<<NB_A, 256, 0, s3>>>(0, MSPLIT);
    cudaEventRecord(evAa, s3);
    cudaStreamWaitEvent(s3, evG1b, 0);
    agg_kernel<<<NB_B, 256, 0, s3>>>(MSPLIT, NN);
    cudaEventRecord(evAb, s3);

    // main: GEMM2 slices (relu fused)
    cudaStreamWaitEvent(0, evAa, 0);
    mma_gemm<<<dim3(DD / 128, MB_A), 256, GEMM_SMEM>>>(
        pTh, pWvh, out, 0, MSPLIT, NP, DD, 1);
    cudaStreamWaitEvent(0, evAb, 0);
    mma_gemm<<<dim3(DD / 128, MB_B), 256, GEMM_SMEM>>>(
        pTh, pWvh, out, MSPLIT, NN, NP, DD, 1);
}

// round 16
// speedup vs baseline: 1.0720x; 1.0004x over previous
#include <cuda_runtime.h>
#include <cuda_fp16.h>
#include <math.h>
#include <stdint.h>

#define NN   50000
#define EE   150000
#define DD   256
#define NP   768          // P columns = 3 * 256
#define SCAN_BLOCKS 49    // ceil(50000/1024)
#define MSPLIT 25088      // 196 * 128

// ------------------------ device scratch (no allocs allowed) ------------------
__device__ int   g_deg [3 * NN];
__device__ int   g_cur [3 * NN];
__device__ int   g_rs  [3 * (NN + 1)];
__device__ int   g_bsum[3 * SCAN_BLOCKS];
__device__ int   g_boff[3 * SCAN_BLOCKS];
__device__ int   g_snbr[3 * 2 * EE];

__device__ __half g_Sh [(size_t)NN * DD];
__device__ __half g_Wah[(size_t)NP * DD];   // [n=r*256+d][k]
__device__ __half g_Wvh[(size_t)DD * NP];   // [n=d][k'=r*256+k]
__device__ float  g_P  [(size_t)NN * NP];   // 153.6 MB
__device__ __half g_Th [(size_t)NN * NP];

// ------------------------ PTX helpers ----------------------------------------
__device__ __forceinline__ uint32_t smem_u32(const void* p) {
    return (uint32_t)__cvta_generic_to_shared(p);
}
__device__ __forceinline__ void cp16(uint32_t dst, const void* src, int srcsz) {
    asm volatile("cp.async.cg.shared.global [%0], [%1], 16, %2;"
                 :: "r"(dst), "l"(src), "r"(srcsz) : "memory");
}
#define CP_COMMIT() asm volatile("cp.async.commit_group;" ::: "memory")
#define CP_WAIT(n)  asm volatile("cp.async.wait_group %0;" :: "n"(n) : "memory")

#define LDSM4(r, addr) asm volatile( \
    "ldmatrix.sync.aligned.m8n8.x4.shared.b16 {%0,%1,%2,%3}, [%4];" \
    : "=r"((r)[0]), "=r"((r)[1]), "=r"((r)[2]), "=r"((r)[3]) : "r"(addr))

#define MMA16816H(d, a, b) asm volatile( \
    "mma.sync.aligned.m16n8k16.row.col.f32.f16.f16.f32 " \
    "{%0,%1,%2,%3}, {%4,%5,%6,%7}, {%8,%9}, {%0,%1,%2,%3};" \
    : "+f"((d)[0]), "+f"((d)[1]), "+f"((d)[2]), "+f"((d)[3]) \
    : "r"((a)[0]), "r"((a)[1]), "r"((a)[2]), "r"((a)[3]), \
      "r"((b)[0]), "r"((b)[1]))

// ------------------------ CSR build ------------------------------------------
__global__ void zero_kernel() {
    int idx = blockIdx.x * blockDim.x + threadIdx.x;
    if (idx < 3 * NN) { g_deg[idx] = 0; g_cur[idx] = 0; }
}

__global__ void degree_kernel(const int* __restrict__ e0,
                              const int* __restrict__ e1,
                              const int* __restrict__ e2) {
    int idx = blockIdx.x * blockDim.x + threadIdx.x;
    if (idx >= 3 * 2 * EE) return;
    int r = idx / (2 * EE);
    int k = idx - r * (2 * EE);
    const int* e = (r == 0) ? e0 : ((r == 1) ? e1 : e2);
    atomicAdd(&g_deg[r * NN + e[k]], 1);
}

__global__ void scan_local() {
    __shared__ int buf[1024];
    int r = blockIdx.y;
    int tid = threadIdx.x;
    int idx = blockIdx.x * 1024 + tid;
    int v = (idx < NN) ? g_deg[r * NN + idx] : 0;
    buf[tid] = v;
    __syncthreads();
    for (int off = 1; off < 1024; off <<= 1) {
        int t = (tid >= off) ? buf[tid - off] : 0;
        __syncthreads();
        buf[tid] += t;
        __syncthreads();
    }
    if (idx < NN) g_rs[r * (NN + 1) + idx] = buf[tid] - v;
    if (tid == 1023) g_bsum[r * SCAN_BLOCKS + blockIdx.x] = buf[1023];
}

__global__ void scan_bsums() {
    int r = threadIdx.x >> 5;
    int lane = threadIdx.x & 31;
    if (r >= 3) return;
    int carry = 0;
    for (int b0 = 0; b0 < SCAN_BLOCKS; b0 += 32) {
        int idx = b0 + lane;
        int orig = (idx < SCAN_BLOCKS) ? g_bsum[r * SCAN_BLOCKS + idx] : 0;
        int v = orig;
#pragma unroll
        for (int off = 1; off < 32; off <<= 1) {
            int t = __shfl_up_sync(0xFFFFFFFFu, v, off);
            if (lane >= off) v += t;
        }
        if (idx < SCAN_BLOCKS) g_boff[r * SCAN_BLOCKS + idx] = carry + v - orig;
        carry += __shfl_sync(0xFFFFFFFFu, v, 31);
    }
    if (lane == 0) g_rs[r * (NN + 1) + NN] = carry;
}

__global__ void scan_add() {
    int r = blockIdx.y;
    int idx = blockIdx.x * 1024 + threadIdx.x;
    if (idx < NN) g_rs[r * (NN + 1) + idx] += g_boff[r * SCAN_BLOCKS + blockIdx.x];
}

__global__ void fill_kernel(const int* __restrict__ e0,
                            const int* __restrict__ e1,
                            const int* __restrict__ e2) {
    int idx = blockIdx.x * blockDim.x + threadIdx.x;
    if (idx >= 3 * EE) return;
    int r = idx / EE;
    int k = idx - r * EE;
    const int* e = (r == 0) ? e0 : ((r == 1) ? e1 : e2);
    int a = e[2 * k], b = e[2 * k + 1];
    int pa = g_rs[r * (NN + 1) + a] + atomicAdd(&g_cur[r * NN + a], 1);
    g_snbr[r * 2 * EE + pa] = b;
    int pb = g_rs[r * (NN + 1) + b] + atomicAdd(&g_cur[r * NN + b], 1);
    g_snbr[r * 2 * EE + pb] = a;
}

// ------------------------ conversions ----------------------------------------
__device__ __forceinline__ void cvt4h(float4 v, __half* hp) {
    ((__half2*)hp)[0] = __halves2half2(__float2half(v.x), __float2half(v.y));
    ((__half2*)hp)[1] = __halves2half2(__float2half(v.z), __float2half(v.w));
}

// converts rows [nbase, nEnd) of S to fp16
__global__ void convertS_kernel(const float* __restrict__ S, int nbase, int nEnd) {
    int idx = nbase * (DD / 4) + blockIdx.x * blockDim.x + threadIdx.x;
    if (idx >= nEnd * (DD / 4)) return;
    float4 v = ((const float4*)S)[idx];
    cvt4h(v, g_Sh + (size_t)idx * 4);
}

// Wa[n=r*256+d][k] = A_r[k][d] = sum_j WQ_r[j][k] * WK_r[j][d]
__global__ void build_wa(const float* __restrict__ WQ,
                         const float* __restrict__ WK) {
    int b = blockIdx.x;            // 0..767
    int r = b >> 8;
    int k = b & 255;
    int d = threadIdx.x;           // 0..255
    const float* wq = WQ + r * 65536;
    const float* wk = WK + r * 65536;
    float acc = 0.f;
#pragma unroll 8
    for (int j = 0; j < 256; j++)
        acc += wq[j * 256 + k] * wk[j * 256 + d];
    g_Wah[(size_t)(r * 256 + d) * DD + k] = __float2half(acc);
}

// Wv[n=d][k'=r*256+k] = W_r[d][k]
__global__ void build_wv(const float* __restrict__ W) {
    int idx = blockIdx.x * blockDim.x + threadIdx.x;
    if (idx >= DD * NP) return;
    int d  = idx / NP;
    int rk = idx - d * NP;
    int r  = rk >> 8;
    int k  = rk & 255;
    g_Wvh[idx] = __float2half(W[r * 65536 + d * 256 + k]);
}

// ------------------------ mma.sync fp16 single-product GEMM ------------------
// C = A @ B^T, fp16 inputs, fp32 accum. BM=128, BN=128, BK=64, 256 threads
// (2x4 warps, warp tile 64x32), 3-stage cp.async pipeline, SW128-style swizzle.
#define STG      32768
#define GEMM_SMEM (3 * STG)

__global__ void __launch_bounds__(256)
mma_gemm(const __half* __restrict__ A, const __half* __restrict__ B,
         float* __restrict__ C, int mbase, int mEnd, int K, int N, int relu) {
    extern __shared__ char smem[];
    const uint32_t sbase = smem_u32(smem);
    const int t = threadIdx.x;
    const int w = t >> 5, l = t & 31;
    const int wm = (w >> 2) * 64;
    const int wn = (w & 3) * 32;
    const int bm = mbase + blockIdx.y * 128;
    const int n0 = blockIdx.x * 128;

    const int lrow = t >> 1;
    const int half = t & 1;
    int mrow = bm + lrow;
    int av = (mrow < mEnd) ? 16 : 0;
    const __half* aRow = A + (size_t)((mrow < mEnd) ? mrow : 0) * K;
    const __half* bRow = B + (size_t)(n0 + lrow) * K;
    const uint32_t aDst = sbase + lrow * 128;
    const uint32_t bDst = sbase + 16384 + lrow * 128;

    float acc[4][4][4];
#pragma unroll
    for (int i = 0; i < 4; i++)
#pragma unroll
        for (int j = 0; j < 4; j++)
#pragma unroll
            for (int q = 0; q < 4; q++) acc[i][j][q] = 0.f;

    auto load_stage = [&](int s, int kt) {
        uint32_t so = (uint32_t)s * STG;
#pragma unroll
        for (int c = 0; c < 4; c++) {
            int chunk = half * 4 + c;
            uint32_t sw = (uint32_t)((chunk ^ (lrow & 7)) << 4);
            cp16(aDst + so + sw, aRow + kt * 64 + chunk * 8, av);
            cp16(bDst + so + sw, bRow + kt * 64 + chunk * 8, 16);
        }
    };

    auto compute = [&](int s) {
        uint32_t aB = sbase + (uint32_t)s * STG;
        uint32_t bB = aB + 16384;
#pragma unroll
        for (int ks = 0; ks < 4; ks++) {
            uint32_t Af[4][4];
#pragma unroll
            for (int im = 0; im < 4; im++) {
                int row = wm + im * 16 + (l & 15);
                int ch = ks * 2 + (l >> 4);
                LDSM4(Af[im], aB + row * 128 + ((ch ^ (row & 7)) << 4));
            }
            uint32_t Bf[4][2];
#pragma unroll
            for (int p = 0; p < 2; p++) {
                int row = wn + p * 16 + (l & 7) + ((l >> 4) & 1) * 8;
                int ch = ks * 2 + ((l >> 3) & 1);
                uint32_t r4[4];
                LDSM4(r4, bB + row * 128 + ((ch ^ (row & 7)) << 4));
                Bf[p * 2][0] = r4[0]; Bf[p * 2][1] = r4[1];
                Bf[p * 2 + 1][0] = r4[2]; Bf[p * 2 + 1][1] = r4[3];
            }
#pragma unroll
            for (int im = 0; im < 4; im++)
#pragma unroll
                for (int in = 0; in < 4; in++)
                    MMA16816H(acc[im][in], Af[im], Bf[in]);
        }
    };

    const int KT = K / 64;
    load_stage(0, 0); CP_COMMIT();
    load_stage(1, 1); CP_COMMIT();
    int s = 0;
    for (int kt = 0; kt < KT; kt++) {
        if (kt < KT - 1) { CP_WAIT(1); } else { CP_WAIT(0); }
        __syncthreads();
        if (kt + 2 < KT) {
            int s2 = s + 2; if (s2 >= 3) s2 -= 3;
            load_stage(s2, kt + 2);
            CP_COMMIT();
        }
        compute(s);
        if (++s == 3) s = 0;
    }

#pragma unroll
    for (int im = 0; im < 4; im++) {
        int r0 = bm + wm + im * 16 + (l >> 2);
#pragma unroll
        for (int in = 0; in < 4; in++) {
            int cc = n0 + wn + in * 8 + (l & 3) * 2;
            float* a4 = acc[im][in];
            if (relu) {
                a4[0] = fmaxf(a4[0], 0.f); a4[1] = fmaxf(a4[1], 0.f);
                a4[2] = fmaxf(a4[2], 0.f); a4[3] = fmaxf(a4[3], 0.f);
            }
            if (r0 < mEnd)
                *(float2*)(C + (size_t)r0 * N + cc) = make_float2(a4[0], a4[1]);
            if (r0 + 8 < mEnd)
                *(float2*)(C + (size_t)(r0 + 8) * N + cc) = make_float2(a4[2], a4[3]);
        }
    }
}

// ------------------------ fused attention aggregation (fp16 gathers) ---------
// Warp per node; lane l owns elements 8l..8l+7 (one 16B fp16 load per edge).
__global__ __launch_bounds__(256)
void agg_kernel(int nbase, int nEnd) {
    int w = threadIdx.x >> 5;
    int l = threadIdx.x & 31;
    int i = nbase + blockIdx.x * 8 + w;
    if (i >= nEnd) return;

    for (int r = 0; r < 3; r++) {
        float acc[8];
#pragma unroll
        for (int q = 0; q < 8; q++) acc[q] = 0.f;
        int start = g_rs[r * (NN + 1) + i];
        int deg   = g_rs[r * (NN + 1) + i + 1] - start;

        if (deg > 0) {
            const float* Pb = g_P + (size_t)i * NP + r * 256 + 8 * l;
            float4 p0 = *(const float4*)(Pb);
            float4 p1 = *(const float4*)(Pb + 4);
            float p[8] = {p0.x, p0.y, p0.z, p0.w, p1.x, p1.y, p1.z, p1.w};
            const int* nb = g_snbr + r * 2 * EE + start;

            float z = 0.f;
            for (int j = 0; j < deg; j++) {
                int nbr = nb[j];
                uint4 raw = *(const uint4*)(g_Sh + (size_t)nbr * DD + 8 * l);
                float sv[8];
                float2 f;
                f = __half22float2(*(__half2*)&raw.x); sv[0] = f.x; sv[1] = f.y;
                f = __half22float2(*(__half2*)&raw.y); sv[2] = f.x; sv[3] = f.y;
                f = __half22float2(*(__half2*)&raw.z); sv[4] = f.x; sv[5] = f.y;
                f = __half22float2(*(__half2*)&raw.w); sv[6] = f.x; sv[7] = f.y;
                float d = 0.f;
#pragma unroll
                for (int q = 0; q < 8; q++) d += p[q] * sv[q];
#pragma unroll
                for (int off = 16; off; off >>= 1)
                    d += __shfl_xor_sync(0xFFFFFFFFu, d, off);
                float e = __expf(d * 0.125f);
                z += e;
#pragma unroll
                for (int q = 0; q < 8; q++) acc[q] += e * sv[q];
            }
            float zi = 1.f / z;
#pragma unroll
            for (int q = 0; q < 8; q++) acc[q] *= zi;
        }
        __half* tp = g_Th + (size_t)i * NP + r * 256 + 8 * l;
        cvt4h(make_float4(acc[0], acc[1], acc[2], acc[3]), tp);
        cvt4h(make_float4(acc[4], acc[5], acc[6], acc[7]), tp + 4);
    }
}

// ------------------------ launch --------------------------------------------
extern "C" void kernel_launch(void* const* d_in, const int* in_sizes, int n_in,
                              void* d_out, int out_size) {
    const float* S  = (const float*)d_in[0];
    const int*   et = (const int*)d_in[1];
    const int*   ec = (const int*)d_in[2];
    const int*   e2 = (const int*)d_in[3];
    const float* W  = (const float*)d_in[4];
    const float* WQ = (const float*)d_in[5];
    const float* WK = (const float*)d_in[6];
    float* out = (float*)d_out;

    static bool init = false;
    static __half *pSh, *pWah, *pWvh, *pTh;
    static float* pP;
    static cudaStream_t s1, s2, s3;
    static cudaEvent_t evFork, evCSR, evW, evCvB, evG1a, evG1b, evAa, evAb, evDone;
    if (!init) {
        cudaGetSymbolAddress((void**)&pSh,  g_Sh);
        cudaGetSymbolAddress((void**)&pWah, g_Wah);
        cudaGetSymbolAddress((void**)&pWvh, g_Wvh);
        cudaGetSymbolAddress((void**)&pTh,  g_Th);
        cudaGetSymbolAddress((void**)&pP,   g_P);
        cudaFuncSetAttribute(mma_gemm, cudaFuncAttributeMaxDynamicSharedMemorySize,
                             GEMM_SMEM);
        int loPri, hiPri;
        cudaDeviceGetStreamPriorityRange(&loPri, &hiPri);
        cudaStreamCreateWithFlags(&s1, cudaStreamNonBlocking);
        cudaStreamCreateWithFlags(&s2, cudaStreamNonBlocking);
        cudaStreamCreateWithPriority(&s3, cudaStreamNonBlocking, hiPri);
        cudaEventCreateWithFlags(&evFork, cudaEventDisableTiming);
        cudaEventCreateWithFlags(&evCSR,  cudaEventDisableTiming);
        cudaEventCreateWithFlags(&evW,    cudaEventDisableTiming);
        cudaEventCreateWithFlags(&evCvB,  cudaEventDisableTiming);
        cudaEventCreateWithFlags(&evG1a,  cudaEventDisableTiming);
        cudaEventCreateWithFlags(&evG1b,  cudaEventDisableTiming);
        cudaEventCreateWithFlags(&evAa,   cudaEventDisableTiming);
        cudaEventCreateWithFlags(&evAb,   cudaEventDisableTiming);
        cudaEventCreateWithFlags(&evDone, cudaEventDisableTiming);
        init = true;
    }

    const int MB_A = MSPLIT / 128;                 // 196
    const int MB_B = (NN - MSPLIT + 127) / 128;    // 195
    const int NB_A = (MSPLIT + 7) / 8;
    const int NB_B = (NN - MSPLIT + 7) / 8;

    // fork
    cudaEventRecord(evFork, 0);
    cudaStreamWaitEvent(s1, evFork, 0);
    cudaStreamWaitEvent(s2, evFork, 0);
    cudaStreamWaitEvent(s3, evFork, 0);

    // s1: CSR build chain
    zero_kernel<<<(3 * NN + 255) / 256, 256, 0, s1>>>();
    degree_kernel<<<(3 * 2 * EE + 255) / 256, 256, 0, s1>>>(et, ec, e2);
    scan_local<<<dim3(SCAN_BLOCKS, 3), 1024, 0, s1>>>();
    scan_bsums<<<1, 96, 0, s1>>>();
    scan_add<<<dim3(SCAN_BLOCKS, 3), 1024, 0, s1>>>();
    fill_kernel<<<(3 * EE + 255) / 256, 256, 0, s1>>>(et, ec, e2);
    cudaEventRecord(evCSR, s1);

    // s2: weight prep + convert S slice b (overlaps conv_a + G1a on main)
    build_wa<<<NP, 256, 0, s2>>>(WQ, WK);
    build_wv<<<(DD * NP + 255) / 256, 256, 0, s2>>>(W);
    cudaEventRecord(evW, s2);
    {
        int n4 = (NN - MSPLIT) * (DD / 4);
        convertS_kernel<<<(n4 + 255) / 256, 256, 0, s2>>>(S, MSPLIT, NN);
    }
    cudaEventRecord(evCvB, s2);

    // main: convert S slice a, then GEMM1 slices
    {
        int n4 = MSPLIT * (DD / 4);
        convertS_kernel<<<(n4 + 255) / 256, 256>>>(S, 0, MSPLIT);
    }
    cudaStreamWaitEvent(0, evW, 0);
    mma_gemm<<<dim3(NP / 128, MB_A), 256, GEMM_SMEM>>>(
        pSh, pWah, pP, 0, MSPLIT, DD, NP, 0);
    cudaEventRecord(evG1a, 0);
    cudaStreamWaitEvent(0, evCvB, 0);
    mma_gemm<<<dim3(NP / 128, MB_B), 256, GEMM_SMEM>>>(
        pSh, pWah, pP, MSPLIT, NN, DD, NP, 0);
    cudaEventRecord(evG1b, 0);

    // s3 (hi-pri): agg slices, each gated on its GEMM1 slice + CSR
    cudaStreamWaitEvent(s3, evCSR, 0);
    cudaStreamWaitEvent(s3, evG1a, 0);
    agg_kernel<<<NB_A, 256, 0, s3>>>(0, MSPLIT);
    cudaEventRecord(evAa, s3);
    cudaStreamWaitEvent(s3, evG1b, 0);
    agg_kernel<<<NB_B, 256, 0, s3>>>(MSPLIT, NN);
    cudaEventRecord(evAb, s3);

    // s2: GEMM2 slices — G2a runs CONCURRENT with G1b (fills partial waves)
    cudaStreamWaitEvent(s2, evAa, 0);
    mma_gemm<<<dim3(DD / 128, MB_A), 256, GEMM_SMEM, s2>>>(
        pTh, pWvh, out, 0, MSPLIT, NP, DD, 1);
    cudaStreamWaitEvent(s2, evAb, 0);
    mma_gemm<<<dim3(DD / 128, MB_B), 256, GEMM_SMEM, s2>>>(
        pTh, pWvh, out, MSPLIT, NN, NP, DD, 1);
    cudaEventRecord(evDone, s2);

    // join all side-stream work back into the capture stream
    cudaStreamWaitEvent(0, evDone, 0);
}